// round 1
// baseline (speedup 1.0000x reference)
#include <cuda_runtime.h>
#include <math.h>

// Problem constants
#define N_CAPS 64
#define CAPS_DIM 16
#define OUT_DIM 128
#define P_DIM 1152
#define BATCH 256
#define BO (BATCH * OUT_DIM)       // 32768
#define PSPLIT 8
#define PCHUNK (P_DIM / PSPLIT)    // 144

// Scratch (no cudaMalloc allowed)
__device__ __align__(16) float g_partial[PSPLIT * BO];   // 1 MB
__device__ __align__(16) float g_wsum[N_CAPS * OUT_DIM]; // 32 KB

// ---------------------------------------------------------------------------
// Kernel 1: X partials. x is (P, B, O) contiguous => matrix (P, 32768).
// Each thread owns one float4 column, sums PCHUNK rows. Streaming loads.
// grid (32, PSPLIT) x block 256  => 65536 threads, ~14 warps/SM.
// ---------------------------------------------------------------------------
__global__ void __launch_bounds__(256) reduce_x_kernel(const float4* __restrict__ x4) {
    int col   = blockIdx.x * blockDim.x + threadIdx.x;  // 0..8191 (float4 units)
    int chunk = blockIdx.y;
    const float4* base = x4 + (size_t)(chunk * PCHUNK) * (BO / 4) + col;

    float4 acc = make_float4(0.f, 0.f, 0.f, 0.f);
#pragma unroll 8
    for (int p = 0; p < PCHUNK; ++p) {
        float4 v = __ldcs(&base[(size_t)p * (BO / 4)]);
        acc.x += v.x; acc.y += v.y; acc.z += v.z; acc.w += v.w;
    }
    reinterpret_cast<float4*>(g_partial)[chunk * (BO / 4) + col] = acc;
}

// ---------------------------------------------------------------------------
// Kernel 2: Wsum[n,o] = sum_c w[n,c,o].  8192 threads.
// ---------------------------------------------------------------------------
__global__ void __launch_bounds__(256) wsum_kernel(const float* __restrict__ w) {
    int i = blockIdx.x * blockDim.x + threadIdx.x;      // 0..8191
    int n = i >> 7, o = i & 127;
    float s = 0.f;
#pragma unroll
    for (int c = 0; c < CAPS_DIM; ++c)
        s += w[n * (CAPS_DIM * OUT_DIM) + c * OUT_DIM + o];
    g_wsum[i] = s;
}

// ---------------------------------------------------------------------------
// Kernel 3: routing. One block per batch element, 128 threads (thread t = o).
//   xp[b,n,o] = X[o] * W[n,o] (never materialized)
//   s_o       = X[o] * sum_n c_n W[n,o]
//   squash    : scale = ||s|| / (1 + ||s||^2)
//   logits_n += sum_o (routed_o * X[o]) * W[n,o]
// ---------------------------------------------------------------------------
__global__ void __launch_bounds__(128) routing_kernel(float* __restrict__ out) {
    const int b = blockIdx.x;
    const int t = threadIdx.x;

    __shared__ float shP[128 * 65];   // padded: conflict-free both directions
    __shared__ float shc[N_CAPS];     // coeffs
    __shared__ float shl[N_CAPS];     // logits
    __shared__ float shred[4];
    __shared__ float shscale;

    // Finalize X[b, t] from the PSPLIT partials
    float X = 0.f;
#pragma unroll
    for (int ch = 0; ch < PSPLIT; ++ch)
        X += g_partial[ch * BO + b * OUT_DIM + t];

    // W column for this o into registers: wreg[n] = Wsum[n][t]
    float wreg[N_CAPS];
#pragma unroll
    for (int n = 0; n < N_CAPS; ++n)
        wreg[n] = g_wsum[n * OUT_DIM + t];

    if (t < N_CAPS) { shl[t] = 0.f; shc[t] = 1.0f / N_CAPS; }
    __syncthreads();

    // ITERATIONS = 3 -> 2 routing updates, then final squash
    for (int iter = 0; iter < 3; ++iter) {
        // s_o = X * sum_n c_n * W[n,o]
        float s = 0.f;
#pragma unroll
        for (int n = 0; n < N_CAPS; ++n)
            s += shc[n] * wreg[n];
        s *= X;

        // block reduce ||s||^2 over 128 threads
        float sq = s * s;
#pragma unroll
        for (int off = 16; off > 0; off >>= 1)
            sq += __shfl_xor_sync(0xffffffffu, sq, off);
        if ((t & 31) == 0) shred[t >> 5] = sq;
        __syncthreads();
        if (t == 0) {
            float tot  = shred[0] + shred[1] + shred[2] + shred[3];
            float norm = sqrtf(tot);
            shscale = norm / (1.0f + tot);   // norm / (1 + norm^2)
        }
        __syncthreads();
        float scale = shscale;

        if (iter == 2) {
            out[b * OUT_DIM + t] = scale * s;   // final squash(coeffs @ xp)
            return;
        }

        // logits_n += sum_o (scale*s_o*X_o) * W[n,o]
        float rp = scale * s * X;
#pragma unroll
        for (int n = 0; n < N_CAPS; ++n)
            shP[t * 65 + n] = rp * wreg[n];
        __syncthreads();
        if (t < N_CAPS) {
            float acc = shl[t];
#pragma unroll 8
            for (int u = 0; u < 128; ++u)
                acc += shP[u * 65 + t];
            shl[t] = acc;
        }
        __syncthreads();

        // softmax over 64 logits, done by warp 0 (2 values per lane)
        if (t < 32) {
            float a  = shl[t];
            float bb = shl[t + 32];
            float m  = fmaxf(a, bb);
#pragma unroll
            for (int off = 16; off > 0; off >>= 1)
                m = fmaxf(m, __shfl_xor_sync(0xffffffffu, m, off));
            float e1 = expf(a - m);
            float e2 = expf(bb - m);
            float sm = e1 + e2;
#pragma unroll
            for (int off = 16; off > 0; off >>= 1)
                sm += __shfl_xor_sync(0xffffffffu, sm, off);
            float inv = 1.0f / sm;
            shc[t]      = e1 * inv;
            shc[t + 32] = e2 * inv;
        }
        __syncthreads();
    }
}

// ---------------------------------------------------------------------------
extern "C" void kernel_launch(void* const* d_in, const int* in_sizes, int n_in,
                              void* d_out, int out_size) {
    const float* x = (const float*)d_in[0];             // (1152, 256, 128)
    const float* w = (const float*)d_in[1];             // (64, 16, 128)
    float* out = (float*)d_out;                         // (256, 1, 128)

    dim3 g1(32, PSPLIT);
    reduce_x_kernel<<<g1, 256>>>(reinterpret_cast<const float4*>(x));
    wsum_kernel<<<32, 256>>>(w);
    routing_kernel<<<BATCH, 128>>>(out);
}

// round 2
// speedup vs baseline: 1.1623x; 1.1623x over previous
#include <cuda_runtime.h>
#include <math.h>

// Problem constants
#define N_CAPS 64
#define CAPS_DIM 16
#define OUT_DIM 128
#define P_DIM 1152
#define BATCH 256
#define BO (BATCH * OUT_DIM)       // 32768
#define PSPLIT 18
#define PCHUNK (P_DIM / PSPLIT)    // 64

// Scratch (no cudaMalloc allowed)
__device__ __align__(16) float g_partial[PSPLIT * BO];   // 2.25 MB
__device__ __align__(16) float g_wsum[N_CAPS * OUT_DIM]; // 32 KB

// ---------------------------------------------------------------------------
// Kernel 1: X partials. x is (P, B, O) contiguous => matrix (P, 32768).
// Each thread owns one float4 column within one P-chunk, sums PCHUNK rows.
// grid (32, PSPLIT=18) x block 256 => 576 blocks (~3.9 blocks/SM, occ ~48%).
// ---------------------------------------------------------------------------
__global__ void __launch_bounds__(256) reduce_x_kernel(const float4* __restrict__ x4) {
    int col   = blockIdx.x * blockDim.x + threadIdx.x;  // 0..8191 (float4 units)
    int chunk = blockIdx.y;
    const float4* base = x4 + (size_t)(chunk * PCHUNK) * (BO / 4) + col;

    float4 acc = make_float4(0.f, 0.f, 0.f, 0.f);
#pragma unroll 8
    for (int p = 0; p < PCHUNK; ++p) {
        float4 v = __ldcs(&base[(size_t)p * (BO / 4)]);
        acc.x += v.x; acc.y += v.y; acc.z += v.z; acc.w += v.w;
    }
    reinterpret_cast<float4*>(g_partial)[chunk * (BO / 4) + col] = acc;
}

// ---------------------------------------------------------------------------
// Kernel 2: Wsum[n,o] = sum_c w[n,c,o].  8192 threads. (launched first — no
// dependency on kernel 1, keeps it off the critical tail)
// ---------------------------------------------------------------------------
__global__ void __launch_bounds__(256) wsum_kernel(const float* __restrict__ w) {
    int i = blockIdx.x * blockDim.x + threadIdx.x;      // 0..8191
    int n = i >> 7, o = i & 127;
    float s = 0.f;
#pragma unroll
    for (int c = 0; c < CAPS_DIM; ++c)
        s += w[n * (CAPS_DIM * OUT_DIM) + c * OUT_DIM + o];
    g_wsum[i] = s;
}

// ---------------------------------------------------------------------------
// Kernel 3: routing. One block per batch element, 128 threads (thread t = o).
//   xp[b,n,o] = X[o] * W[n,o] (never materialized)
//   s_o       = X[o] * sum_n c_n W[n,o]
//   squash    : scale = ||s|| / (1 + ||s||^2)
//   logits_n += sum_o (routed_o * X[o]) * W[n,o]
// ---------------------------------------------------------------------------
__global__ void __launch_bounds__(128) routing_kernel(float* __restrict__ out) {
    const int b = blockIdx.x;
    const int t = threadIdx.x;

    __shared__ float shP[128 * 65];   // padded: conflict-free both directions
    __shared__ float shc[N_CAPS];     // coeffs
    __shared__ float shl[N_CAPS];     // logits
    __shared__ float shred[4];
    __shared__ float shscale;

    // Finalize X[b, t] from the PSPLIT partials
    float X = 0.f;
#pragma unroll
    for (int ch = 0; ch < PSPLIT; ++ch)
        X += g_partial[ch * BO + b * OUT_DIM + t];

    // W column for this o into registers: wreg[n] = Wsum[n][t]
    float wreg[N_CAPS];
#pragma unroll
    for (int n = 0; n < N_CAPS; ++n)
        wreg[n] = g_wsum[n * OUT_DIM + t];

    if (t < N_CAPS) { shl[t] = 0.f; shc[t] = 1.0f / N_CAPS; }
    __syncthreads();

    // ITERATIONS = 3 -> 2 routing updates, then final squash
    for (int iter = 0; iter < 3; ++iter) {
        // s_o = X * sum_n c_n * W[n,o]
        float s = 0.f;
#pragma unroll
        for (int n = 0; n < N_CAPS; ++n)
            s += shc[n] * wreg[n];
        s *= X;

        // block reduce ||s||^2 over 128 threads
        float sq = s * s;
#pragma unroll
        for (int off = 16; off > 0; off >>= 1)
            sq += __shfl_xor_sync(0xffffffffu, sq, off);
        if ((t & 31) == 0) shred[t >> 5] = sq;
        __syncthreads();
        if (t == 0) {
            float tot  = shred[0] + shred[1] + shred[2] + shred[3];
            float norm = sqrtf(tot);
            shscale = norm / (1.0f + tot);   // norm / (1 + norm^2)
        }
        __syncthreads();
        float scale = shscale;

        if (iter == 2) {
            out[b * OUT_DIM + t] = scale * s;   // final squash(coeffs @ xp)
            return;
        }

        // logits_n += sum_o (scale*s_o*X_o) * W[n,o]
        float rp = scale * s * X;
#pragma unroll
        for (int n = 0; n < N_CAPS; ++n)
            shP[t * 65 + n] = rp * wreg[n];
        __syncthreads();
        if (t < N_CAPS) {
            float acc = shl[t];
#pragma unroll 8
            for (int u = 0; u < 128; ++u)
                acc += shP[u * 65 + t];
            shl[t] = acc;
        }
        __syncthreads();

        // softmax over 64 logits, done by warp 0 (2 values per lane)
        if (t < 32) {
            float a  = shl[t];
            float bb = shl[t + 32];
            float m  = fmaxf(a, bb);
#pragma unroll
            for (int off = 16; off > 0; off >>= 1)
                m = fmaxf(m, __shfl_xor_sync(0xffffffffu, m, off));
            float e1 = expf(a - m);
            float e2 = expf(bb - m);
            float sm = e1 + e2;
#pragma unroll
            for (int off = 16; off > 0; off >>= 1)
                sm += __shfl_xor_sync(0xffffffffu, sm, off);
            float inv = 1.0f / sm;
            shc[t]      = e1 * inv;
            shc[t + 32] = e2 * inv;
        }
        __syncthreads();
    }
}

// ---------------------------------------------------------------------------
extern "C" void kernel_launch(void* const* d_in, const int* in_sizes, int n_in,
                              void* d_out, int out_size) {
    const float* x = (const float*)d_in[0];             // (1152, 256, 128)
    const float* w = (const float*)d_in[1];             // (64, 16, 128)
    float* out = (float*)d_out;                         // (256, 1, 128)

    wsum_kernel<<<32, 256>>>(w);                         // tiny, no deps on k1
    dim3 g1(32, PSPLIT);
    reduce_x_kernel<<<g1, 256>>>(reinterpret_cast<const float4*>(x));
    routing_kernel<<<BATCH, 128>>>(out);
}

// round 3
// speedup vs baseline: 1.1971x; 1.0300x over previous
#include <cuda_runtime.h>
#include <math.h>

// Problem constants
#define N_CAPS 64
#define CAPS_DIM 16
#define OUT_DIM 128
#define P_DIM 1152
#define BATCH 256
#define BO (BATCH * OUT_DIM)       // 32768
#define PSPLIT 18
#define PCHUNK (P_DIM / PSPLIT)    // 64

// Scratch (no cudaMalloc allowed)
__device__ __align__(16) float g_partial[PSPLIT * BO];   // 2.25 MB
__device__ __align__(16) float g_wsum[N_CAPS * OUT_DIM]; // 32 KB

// ---------------------------------------------------------------------------
// Kernel 1 (fused): grid (32, PSPLIT+1) x 256.
//  y < PSPLIT : X partials. x is (P, B, O) => matrix (P, 32768 floats).
//               Each thread owns one float4 column, sums PCHUNK rows.
//  y == PSPLIT: Wsum[n,o] = sum_c w[n,c,o], float4-vectorized, runs
//               concurrently with (hidden inside) the HBM-bound reduction.
// ---------------------------------------------------------------------------
__global__ void __launch_bounds__(256) reduce_x_kernel(const float4* __restrict__ x4,
                                                       const float4* __restrict__ w4) {
    int chunk = blockIdx.y;

    if (chunk == PSPLIT) {
        // Wsum slice: 64*128 floats = 2048 float4 outputs; blocks 0..7 active.
        int i = blockIdx.x * blockDim.x + threadIdx.x;   // float4 index
        if (i >= N_CAPS * (OUT_DIM / 4)) return;
        int n  = i >> 5;              // /32 float4s per row of 128
        int o4 = i & 31;
        const float4* base = w4 + (size_t)n * (CAPS_DIM * OUT_DIM / 4) + o4;
        float4 acc = make_float4(0.f, 0.f, 0.f, 0.f);
#pragma unroll
        for (int c = 0; c < CAPS_DIM; ++c) {
            float4 v = __ldg(&base[c * (OUT_DIM / 4)]);
            acc.x += v.x; acc.y += v.y; acc.z += v.z; acc.w += v.w;
        }
        reinterpret_cast<float4*>(g_wsum)[i] = acc;
        return;
    }

    int col = blockIdx.x * blockDim.x + threadIdx.x;     // 0..8191 (float4 units)
    const float4* base = x4 + (size_t)(chunk * PCHUNK) * (BO / 4) + col;

    float4 acc = make_float4(0.f, 0.f, 0.f, 0.f);
#pragma unroll 8
    for (int p = 0; p < PCHUNK; ++p) {
        float4 v = __ldcs(&base[(size_t)p * (BO / 4)]);
        acc.x += v.x; acc.y += v.y; acc.z += v.z; acc.w += v.w;
    }
    reinterpret_cast<float4*>(g_partial)[chunk * (BO / 4) + col] = acc;
}

// ---------------------------------------------------------------------------
// Kernel 2: routing. One block per batch element, 128 threads (thread t = o).
//   xp[b,n,o] = X[o] * W[n,o] (never materialized)
//   s_o       = X[o] * sum_n c_n W[n,o]
//   squash    : scale = ||s|| / (1 + ||s||^2)
//   logits_n += sum_o (routed_o * X[o]) * W[n,o]
// ---------------------------------------------------------------------------
__global__ void __launch_bounds__(128) routing_kernel(float* __restrict__ out) {
    const int b = blockIdx.x;
    const int t = threadIdx.x;

    __shared__ float shP[128 * 65];   // padded: conflict-free both directions
    __shared__ float shc[N_CAPS];     // coeffs
    __shared__ float shl[N_CAPS];     // logits
    __shared__ float shred[4];
    __shared__ float shscale;

    // Finalize X[b, t] from the PSPLIT partials
    float X = 0.f;
#pragma unroll
    for (int ch = 0; ch < PSPLIT; ++ch)
        X += g_partial[ch * BO + b * OUT_DIM + t];

    // W column for this o into registers: wreg[n] = Wsum[n][t]
    float wreg[N_CAPS];
#pragma unroll
    for (int n = 0; n < N_CAPS; ++n)
        wreg[n] = g_wsum[n * OUT_DIM + t];

    if (t < N_CAPS) { shl[t] = 0.f; shc[t] = 1.0f / N_CAPS; }
    __syncthreads();

    // ITERATIONS = 3 -> 2 routing updates, then final squash
    for (int iter = 0; iter < 3; ++iter) {
        // s_o = X * sum_n c_n * W[n,o]
        float s = 0.f;
#pragma unroll
        for (int n = 0; n < N_CAPS; ++n)
            s += shc[n] * wreg[n];
        s *= X;

        // block reduce ||s||^2 over 128 threads
        float sq = s * s;
#pragma unroll
        for (int off = 16; off > 0; off >>= 1)
            sq += __shfl_xor_sync(0xffffffffu, sq, off);
        if ((t & 31) == 0) shred[t >> 5] = sq;
        __syncthreads();
        if (t == 0) {
            float tot  = shred[0] + shred[1] + shred[2] + shred[3];
            float norm = sqrtf(tot);
            shscale = norm / (1.0f + tot);   // norm / (1 + norm^2)
        }
        __syncthreads();
        float scale = shscale;

        if (iter == 2) {
            out[b * OUT_DIM + t] = scale * s;   // final squash(coeffs @ xp)
            return;
        }

        // logits_n += sum_o (scale*s_o*X_o) * W[n,o]
        float rp = scale * s * X;
#pragma unroll
        for (int n = 0; n < N_CAPS; ++n)
            shP[t * 65 + n] = rp * wreg[n];
        __syncthreads();
        if (t < N_CAPS) {
            float acc = shl[t];
#pragma unroll 8
            for (int u = 0; u < 128; ++u)
                acc += shP[u * 65 + t];
            shl[t] = acc;
        }
        __syncthreads();

        // softmax over 64 logits, done by warp 0 (2 values per lane)
        if (t < 32) {
            float a  = shl[t];
            float bb = shl[t + 32];
            float m  = fmaxf(a, bb);
#pragma unroll
            for (int off = 16; off > 0; off >>= 1)
                m = fmaxf(m, __shfl_xor_sync(0xffffffffu, m, off));
            float e1 = expf(a - m);
            float e2 = expf(bb - m);
            float sm = e1 + e2;
#pragma unroll
            for (int off = 16; off > 0; off >>= 1)
                sm += __shfl_xor_sync(0xffffffffu, sm, off);
            float inv = 1.0f / sm;
            shc[t]      = e1 * inv;
            shc[t + 32] = e2 * inv;
        }
        __syncthreads();
    }
}

// ---------------------------------------------------------------------------
extern "C" void kernel_launch(void* const* d_in, const int* in_sizes, int n_in,
                              void* d_out, int out_size) {
    const float* x = (const float*)d_in[0];             // (1152, 256, 128)
    const float* w = (const float*)d_in[1];             // (64, 16, 128)
    float* out = (float*)d_out;                         // (256, 1, 128)

    dim3 g1(32, PSPLIT + 1);
    reduce_x_kernel<<<g1, 256>>>(reinterpret_cast<const float4*>(x),
                                 reinterpret_cast<const float4*>(w));
    routing_kernel<<<BATCH, 128>>>(out);
}